// round 15
// baseline (speedup 1.0000x reference)
#include <cuda_runtime.h>
#include <cuda_fp16.h>
#include <cstdint>

#define BATCH 4
#define NL    1024
#define HWN   4096
#define CIN   512
#define CKD   256
#define NH    8
#define DK    32
#define DV    32
#define MTOT  4096
#define EPSI  1e-5f
#define QSCALE 0.09016844f   /* (1/16) * log2(e) */
#define KV_SMEM (3 * 20480)  /* 3 stages x (bh 8K + bl 8K + ah 4K) */

typedef unsigned long long u64;

// ---------------- helpers ----------------
__device__ __forceinline__ float ex2(float x) {
    float r; asm("ex2.approx.f32 %0, %1;" : "=f"(r) : "f"(x)); return r;
}
__device__ __forceinline__ uint32_t h2pack(float lo, float hi) {
    __half2 h = __floats2half2_rn(lo, hi);     // .x = lo half
    return *(uint32_t*)&h;
}
__device__ __forceinline__ uint32_t smem_u32(const void* p) {
    uint32_t a;
    asm("{ .reg .u64 t; cvta.to.shared.u64 t, %1; cvt.u32.u64 %0, t; }"
        : "=r"(a) : "l"(p));
    return a;
}
__device__ __forceinline__ void ldsm4(uint32_t* r, uint32_t addr) {
    asm volatile("ldmatrix.sync.aligned.m8n8.x4.shared.b16 {%0,%1,%2,%3}, [%4];"
        : "=r"(r[0]), "=r"(r[1]), "=r"(r[2]), "=r"(r[3]) : "r"(addr));
}
__device__ __forceinline__ void mma16816(float* c, const uint32_t* a,
                                         const uint32_t b0, const uint32_t b1) {
    asm volatile(
        "mma.sync.aligned.m16n8k16.row.col.f32.f16.f16.f32 "
        "{%0,%1,%2,%3},{%4,%5,%6,%7},{%8,%9},{%0,%1,%2,%3};"
        : "+f"(c[0]), "+f"(c[1]), "+f"(c[2]), "+f"(c[3])
        : "r"(a[0]), "r"(a[1]), "r"(a[2]), "r"(a[3]), "r"(b0), "r"(b1));
}
__device__ __forceinline__ void cpa16(uint32_t dst, const void* src) {
    asm volatile("cp.async.cg.shared.global [%0], [%1], 16;"
        :: "r"(dst), "l"(src) : "memory");
}
#define CP_COMMIT() asm volatile("cp.async.commit_group;" ::: "memory")
#define CP_WAIT0()  asm volatile("cp.async.wait_group 0;" ::: "memory")
#define CP_WAIT1()  asm volatile("cp.async.wait_group 1;" ::: "memory")

// ---------------- scratch ----------------
__device__ __half g_qh[MTOT * CKD];                       // q fp16, prescaled
__device__ __half g_lh[MTOT * CIN];                       // l split hi
__device__ __half g_ll[MTOT * CIN];                       // l split lo
__device__ __half g_wqh[CKD * CIN];                       // Wq fp16
__device__ __half g_xh[(size_t)BATCH * HWN * CIN];        // x split hi
__device__ __half g_xl[(size_t)BATCH * HWN * CIN];        // x split lo
__device__ __half g_wh[512 * CIN];                        // [Wk;Wv] hi
__device__ __half g_wwh[CKD * CKD];                       // Ww fp16
__device__ __half g_k16[(size_t)BATCH * CKD * HWN];       // fp16 [b,c,n] (pre-norm)
__device__ float  g_mu[BATCH * CKD];                      // K row mean
__device__ float  g_rs[BATCH * CKD];                      // K row rstd
__device__ __half g_kh[(size_t)BATCH * NH * HWN * DK];    // [b,h][n][dk] normalized
__device__ __half g_vh[(size_t)BATCH * CKD * HWN];        // [b,c,n]
__device__ __half g_ath[MTOT * CKD];                      // attention out hi
__device__ __half g_atl[MTOT * CKD];                      // attention out lo
__device__ float  g_y[CKD * MTOT];

#define XBLOCKS ((BATCH * HWN * CIN) / (256 * 8))   /* 4096 */
#define LBLOCKS ((MTOT * CIN) / (256 * 8))          /* 1024 */

// ---------------------------------------------------------------------------
// combined split of x and l -> fp16 hi/lo  (blocks < XBLOCKS: x; else l)
// ---------------------------------------------------------------------------
__global__ __launch_bounds__(256) void split_xl_kernel(
    const float* __restrict__ X, const float* __restrict__ L)
{
    const bool isl = blockIdx.x >= XBLOCKS;
    const int blk = isl ? blockIdx.x - XBLOCKS : blockIdx.x;
    const float* src = isl ? L : X;
    __half* dh = isl ? g_lh : g_xh;
    __half* dl = isl ? g_ll : g_xl;
    const size_t i0 = ((size_t)blk * 256 + threadIdx.x) * 8;
    float4 f0 = *(const float4*)(src + i0);
    float4 f1 = *(const float4*)(src + i0 + 4);
    float f[8] = {f0.x, f0.y, f0.z, f0.w, f1.x, f1.y, f1.z, f1.w};
    uint32_t wh[4], wl[4];
    #pragma unroll
    for (int j = 0; j < 4; j++) {
        float a = f[2*j], b = f[2*j+1];
        __half ha = __float2half_rn(a), hb = __float2half_rn(b);
        wh[j] = h2pack(__half2float(ha), __half2float(hb));
        wl[j] = h2pack(a - __half2float(ha), b - __half2float(hb));
    }
    *(uint2*)(dh + i0)     = make_uint2(wh[0], wh[1]);
    *(uint2*)(dh + i0 + 4) = make_uint2(wh[2], wh[3]);
    *(uint2*)(dl + i0)     = make_uint2(wl[0], wl[1]);
    *(uint2*)(dl + i0 + 4) = make_uint2(wl[2], wl[3]);
}

// ---------------------------------------------------------------------------
// weight splits -> fp16 hi
// ---------------------------------------------------------------------------
__global__ __launch_bounds__(256) void split_w_kernel(
    const float* __restrict__ Wk, const float* __restrict__ Wv)
{
    const int row = blockIdx.x;
    const float* src = (row < CKD) ? (Wk + (size_t)row * CIN)
                                   : (Wv + (size_t)(row - CKD) * CIN);
    const int c = threadIdx.x * 2;
    *(uint32_t*)(g_wh + (size_t)row * CIN + c) = h2pack(src[c], src[c + 1]);
}
__global__ __launch_bounds__(256) void split_wq_kernel(const float* __restrict__ Wq)
{
    const int row = blockIdx.x;
    const int c = threadIdx.x * 2;
    *(uint32_t*)(g_wqh + (size_t)row * CIN + c) =
        h2pack(Wq[(size_t)row * CIN + c], Wq[(size_t)row * CIN + c + 1]);
}
__global__ __launch_bounds__(128) void split_ww_kernel(const float* __restrict__ Ww)
{
    const int row = blockIdx.x;
    const int c = threadIdx.x * 2;
    *(uint32_t*)(g_wwh + (size_t)row * CKD + c) =
        h2pack(Ww[(size_t)row * CKD + c], Ww[(size_t)row * CKD + c + 1]);
}

// ---------------------------------------------------------------------------
// HMMA q GEMM: g_qh[m][ck] = (l[m,:].Wq[ck,:] + bq)*QSCALE   (2-term)
// ---------------------------------------------------------------------------
__global__ void __launch_bounds__(256) gemm_q_hmma(const float* __restrict__ bq)
{
    extern __shared__ __align__(16) char dynsm[];
    const int c0 = blockIdx.y << 6;
    const int m0 = blockIdx.x << 7;
    const int t = threadIdx.x, w = t >> 5, lane = t & 31;

    const int xrow = t >> 1, xc2 = (t & 1) << 1;
    const int wrow = t >> 2, wc = t & 3;
    const uint4* pxh = (const uint4*)(g_lh + (size_t)(m0 + xrow) * CIN);
    const uint4* pxl = (const uint4*)(g_ll + (size_t)(m0 + xrow) * CIN);
    const uint4* pwh = (const uint4*)(g_wqh + (size_t)(c0 + wrow) * CIN);

    const int xsw = (xrow >> 1) & 3, wsw = (wrow >> 1) & 3;
    const uint32_t xd0 = (uint32_t)(xrow * 4 + ((xc2)     ^ xsw)) * 16;
    const uint32_t xd1 = (uint32_t)(xrow * 4 + ((xc2 + 1) ^ xsw)) * 16;
    const uint32_t wd  = (uint32_t)(wrow * 4 + (wc ^ wsw)) * 16;

    const uint32_t base = smem_u32(dynsm);
    uint32_t xhB[3], xlB[3], whB[3];
    #pragma unroll
    for (int p = 0; p < 3; p++) {
        xhB[p] = base + p * 20480;
        xlB[p] = xhB[p] + 8192;
        whB[p] = xhB[p] + 16384;
    }

    const int cw = (w & 3) << 4;
    const int nw = (w >> 2) << 6;

    #pragma unroll
    for (int p = 0; p < 2; p++) {
        const int kc = p << 2;
        cpa16(xhB[p] + xd0, pxh + kc + xc2);
        cpa16(xhB[p] + xd1, pxh + kc + xc2 + 1);
        cpa16(xlB[p] + xd0, pxl + kc + xc2);
        cpa16(xlB[p] + xd1, pxl + kc + xc2 + 1);
        cpa16(whB[p] + wd,  pwh + kc + wc);
        CP_COMMIT();
    }

    float C[8][4] = {};
    int stage = 0;

    for (int s = 0; s < 16; s++) {
        if (s == 15) { CP_WAIT0(); } else { CP_WAIT1(); }
        __syncthreads();
        if (s < 14) {
            const int kc = (s + 2) << 2;
            const int nx = (stage + 2 >= 3) ? stage - 1 : stage + 2;
            cpa16(xhB[nx] + xd0, pxh + kc + xc2);
            cpa16(xhB[nx] + xd1, pxh + kc + xc2 + 1);
            cpa16(xlB[nx] + xd0, pxl + kc + xc2);
            cpa16(xlB[nx] + xd1, pxl + kc + xc2 + 1);
            cpa16(whB[nx] + wd,  pwh + kc + wc);
            CP_COMMIT();
        }

        uint32_t Ah[2][4];
        const int arow = cw + (lane & 7) + ((lane >> 3) & 1) * 8;
        const int aswz = (arow >> 1) & 3;
        #pragma unroll
        for (int ks = 0; ks < 2; ks++) {
            const uint32_t aoff = (arow * 4 + (((ks << 1) + (lane >> 4)) ^ aswz)) * 16;
            ldsm4(Ah[ks], whB[stage] + aoff);
        }
        #pragma unroll
        for (int j = 0; j < 8; j++) {
            const int brow = nw + (j << 3) + (lane & 7);
            const uint32_t boff = (brow * 4 + ((lane >> 3) ^ ((brow >> 1) & 3))) * 16;
            uint32_t bh[4], bl[4];
            ldsm4(bh, xhB[stage] + boff);
            ldsm4(bl, xlB[stage] + boff);
            mma16816(C[j], Ah[0], bh[0], bh[1]);
            mma16816(C[j], Ah[1], bh[2], bh[3]);
            mma16816(C[j], Ah[0], bl[0], bl[1]);
            mma16816(C[j], Ah[1], bl[2], bl[3]);
        }
        stage = (stage + 1 == 3) ? 0 : stage + 1;
    }

    const int g = lane >> 2, l = lane & 3;
    const int cc = c0 + cw + g;
    const float b0 = bq[cc], b1 = bq[cc + 8];
    #pragma unroll
    for (int j = 0; j < 8; j++) {
        const int m = m0 + nw + (j << 3) + (l << 1);
        g_qh[(size_t)m * CKD + cc]           = __float2half_rn((C[j][0] + b0) * QSCALE);
        g_qh[(size_t)(m + 1) * CKD + cc]     = __float2half_rn((C[j][1] + b0) * QSCALE);
        g_qh[(size_t)m * CKD + cc + 8]       = __float2half_rn((C[j][2] + b1) * QSCALE);
        g_qh[(size_t)(m + 1) * CKD + cc + 8] = __float2half_rn((C[j][3] + b1) * QSCALE);
    }
}

// ---------------------------------------------------------------------------
// HMMA k/v GEMM, 2-term, 3-stage cp.async.  K -> fp16 g_k16, V -> fp16 g_vh.
// ---------------------------------------------------------------------------
__global__ void __launch_bounds__(256) gemm_kv_hmma(const float* __restrict__ bv)
{
    extern __shared__ __align__(16) char dynsm[];
    const int bat = blockIdx.z;
    const int c0  = blockIdx.y << 6;
    const int n0  = blockIdx.x << 7;
    const int t = threadIdx.x, w = t >> 5, lane = t & 31;

    const int xrow = t >> 1, xc2 = (t & 1) << 1;
    const int wrow = t >> 2, wc = t & 3;
    const uint4* pxh = (const uint4*)(g_xh + (size_t)(bat * HWN + n0 + xrow) * CIN);
    const uint4* pxl = (const uint4*)(g_xl + (size_t)(bat * HWN + n0 + xrow) * CIN);
    const uint4* pwh = (const uint4*)(g_wh + (size_t)(c0 + wrow) * CIN);

    const int xsw = (xrow >> 1) & 3, wsw = (wrow >> 1) & 3;
    const uint32_t xd0 = (uint32_t)(xrow * 4 + ((xc2)     ^ xsw)) * 16;
    const uint32_t xd1 = (uint32_t)(xrow * 4 + ((xc2 + 1) ^ xsw)) * 16;
    const uint32_t wd  = (uint32_t)(wrow * 4 + (wc ^ wsw)) * 16;

    const uint32_t base = smem_u32(dynsm);
    uint32_t xhB[3], xlB[3], whB[3];
    #pragma unroll
    for (int p = 0; p < 3; p++) {
        xhB[p] = base + p * 20480;
        xlB[p] = xhB[p] + 8192;
        whB[p] = xhB[p] + 16384;
    }

    const int cw = (w & 3) << 4;
    const int nw = (w >> 2) << 6;

    #pragma unroll
    for (int p = 0; p < 2; p++) {
        const int kc = p << 2;
        cpa16(xhB[p] + xd0, pxh + kc + xc2);
        cpa16(xhB[p] + xd1, pxh + kc + xc2 + 1);
        cpa16(xlB[p] + xd0, pxl + kc + xc2);
        cpa16(xlB[p] + xd1, pxl + kc + xc2 + 1);
        cpa16(whB[p] + wd,  pwh + kc + wc);
        CP_COMMIT();
    }

    float C[8][4] = {};
    int stage = 0;

    for (int s = 0; s < 16; s++) {
        if (s == 15) { CP_WAIT0(); } else { CP_WAIT1(); }
        __syncthreads();
        if (s < 14) {
            const int kc = (s + 2) << 2;
            const int nx = (stage + 2 >= 3) ? stage - 1 : stage + 2;
            cpa16(xhB[nx] + xd0, pxh + kc + xc2);
            cpa16(xhB[nx] + xd1, pxh + kc + xc2 + 1);
            cpa16(xlB[nx] + xd0, pxl + kc + xc2);
            cpa16(xlB[nx] + xd1, pxl + kc + xc2 + 1);
            cpa16(whB[nx] + wd,  pwh + kc + wc);
            CP_COMMIT();
        }

        uint32_t Ah[2][4];
        const int arow = cw + (lane & 7) + ((lane >> 3) & 1) * 8;
        const int aswz = (arow >> 1) & 3;
        #pragma unroll
        for (int ks = 0; ks < 2; ks++) {
            const uint32_t aoff = (arow * 4 + (((ks << 1) + (lane >> 4)) ^ aswz)) * 16;
            ldsm4(Ah[ks], whB[stage] + aoff);
        }
        #pragma unroll
        for (int j = 0; j < 8; j++) {
            const int brow = nw + (j << 3) + (lane & 7);
            const uint32_t boff = (brow * 4 + ((lane >> 3) ^ ((brow >> 1) & 3))) * 16;
            uint32_t bh[4], bl[4];
            ldsm4(bh, xhB[stage] + boff);
            ldsm4(bl, xlB[stage] + boff);
            mma16816(C[j], Ah[0], bh[0], bh[1]);
            mma16816(C[j], Ah[1], bh[2], bh[3]);
            mma16816(C[j], Ah[0], bl[0], bl[1]);
            mma16816(C[j], Ah[1], bl[2], bl[3]);
        }
        stage = (stage + 1 == 3) ? 0 : stage + 1;
    }

    const int g = lane >> 2, l = lane & 3;
    const int cc = c0 + cw + g;
    if (c0 < CKD) {
        __half* k0p = g_k16 + ((size_t)bat * CKD + cc) * HWN;
        __half* k1p = g_k16 + ((size_t)bat * CKD + cc + 8) * HWN;
        #pragma unroll
        for (int j = 0; j < 8; j++) {
            const int n = n0 + nw + (j << 3) + (l << 1);
            *(uint32_t*)(k0p + n) = h2pack(C[j][0], C[j][1]);
            *(uint32_t*)(k1p + n) = h2pack(C[j][2], C[j][3]);
        }
    } else {
        const int cv = cc - CKD;
        const float b0 = bv[cv], b1 = bv[cv + 8];
        __half* v0p = g_vh + ((size_t)bat * CKD + cv) * HWN;
        __half* v1p = g_vh + ((size_t)bat * CKD + cv + 8) * HWN;
        #pragma unroll
        for (int j = 0; j < 8; j++) {
            const int n = n0 + nw + (j << 3) + (l << 1);
            *(uint32_t*)(v0p + n) = h2pack(C[j][0] + b0, C[j][1] + b0);
            *(uint32_t*)(v1p + n) = h2pack(C[j][2] + b1, C[j][3] + b1);
        }
    }
}

// ---------------------------------------------------------------------------
// HMMA projection GEMM: g_y[o][m] = att[m][:256] . Ww[o][:256]
// ---------------------------------------------------------------------------
__global__ void __launch_bounds__(256) gemm_proj_hmma()
{
    extern __shared__ __align__(16) char dynsm[];
    const int c0 = blockIdx.y << 6;
    const int m0 = blockIdx.x << 7;
    const int t = threadIdx.x, w = t >> 5, lane = t & 31;

    const int xrow = t >> 1, xc2 = (t & 1) << 1;
    const int wrow = t >> 2, wc = t & 3;
    const uint4* pxh = (const uint4*)(g_ath + (size_t)(m0 + xrow) * CKD);
    const uint4* pxl = (const uint4*)(g_atl + (size_t)(m0 + xrow) * CKD);
    const uint4* pwh = (const uint4*)(g_wwh + (size_t)(c0 + wrow) * CKD);

    const int xsw = (xrow >> 1) & 3, wsw = (wrow >> 1) & 3;
    const uint32_t xd0 = (uint32_t)(xrow * 4 + ((xc2)     ^ xsw)) * 16;
    const uint32_t xd1 = (uint32_t)(xrow * 4 + ((xc2 + 1) ^ xsw)) * 16;
    const uint32_t wd  = (uint32_t)(wrow * 4 + (wc ^ wsw)) * 16;

    const uint32_t base = smem_u32(dynsm);
    uint32_t xhB[3], xlB[3], whB[3];
    #pragma unroll
    for (int p = 0; p < 3; p++) {
        xhB[p] = base + p * 20480;
        xlB[p] = xhB[p] + 8192;
        whB[p] = xhB[p] + 16384;
    }

    const int cw = (w & 3) << 4;
    const int nw = (w >> 2) << 6;

    #pragma unroll
    for (int p = 0; p < 2; p++) {
        const int kc = p << 2;
        cpa16(xhB[p] + xd0, pxh + kc + xc2);
        cpa16(xhB[p] + xd1, pxh + kc + xc2 + 1);
        cpa16(xlB[p] + xd0, pxl + kc + xc2);
        cpa16(xlB[p] + xd1, pxl + kc + xc2 + 1);
        cpa16(whB[p] + wd,  pwh + kc + wc);
        CP_COMMIT();
    }

    float C[8][4] = {};
    int stage = 0;

    for (int s = 0; s < 8; s++) {
        if (s == 7) { CP_WAIT0(); } else { CP_WAIT1(); }
        __syncthreads();
        if (s < 6) {
            const int kc = (s + 2) << 2;
            const int nx = (stage + 2 >= 3) ? stage - 1 : stage + 2;
            cpa16(xhB[nx] + xd0, pxh + kc + xc2);
            cpa16(xhB[nx] + xd1, pxh + kc + xc2 + 1);
            cpa16(xlB[nx] + xd0, pxl + kc + xc2);
            cpa16(xlB[nx] + xd1, pxl + kc + xc2 + 1);
            cpa16(whB[nx] + wd,  pwh + kc + wc);
            CP_COMMIT();
        }

        uint32_t Ah[2][4];
        const int arow = cw + (lane & 7) + ((lane >> 3) & 1) * 8;
        const int aswz = (arow >> 1) & 3;
        #pragma unroll
        for (int ks = 0; ks < 2; ks++) {
            const uint32_t aoff = (arow * 4 + (((ks << 1) + (lane >> 4)) ^ aswz)) * 16;
            ldsm4(Ah[ks], whB[stage] + aoff);
        }
        #pragma unroll
        for (int j = 0; j < 8; j++) {
            const int brow = nw + (j << 3) + (lane & 7);
            const uint32_t boff = (brow * 4 + ((lane >> 3) ^ ((brow >> 1) & 3))) * 16;
            uint32_t bh[4], bl[4];
            ldsm4(bh, xhB[stage] + boff);
            ldsm4(bl, xlB[stage] + boff);
            mma16816(C[j], Ah[0], bh[0], bh[1]);
            mma16816(C[j], Ah[1], bh[2], bh[3]);
            mma16816(C[j], Ah[0], bl[0], bl[1]);
            mma16816(C[j], Ah[1], bl[2], bl[3]);
        }
        stage = (stage + 1 == 3) ? 0 : stage + 1;
    }

    const int g = lane >> 2, l = lane & 3;
    const int cc = c0 + cw + g;
    float* y0 = g_y + (size_t)cc * MTOT;
    float* y1 = g_y + (size_t)(cc + 8) * MTOT;
    #pragma unroll
    for (int j = 0; j < 8; j++) {
        const int m = m0 + nw + (j << 3) + (l << 1);
        *(float2*)(y0 + m) = make_float2(C[j][0], C[j][1]);
        *(float2*)(y1 + m) = make_float2(C[j][2], C[j][3]);
    }
}

// ---------------------------------------------------------------------------
// K InstanceNorm stats (fp16 input, fp32 accumulate)
// ---------------------------------------------------------------------------
__global__ __launch_bounds__(256) void inorm_stats_kernel()
{
    __shared__ float red[16];
    const int row = blockIdx.x;
    const uint4* p4 = reinterpret_cast<const uint4*>(g_k16 + (size_t)row * HWN);
    const int t = threadIdx.x;
    float s = 0.f, sq = 0.f;
    #pragma unroll
    for (int i = 0; i < 2; i++) {
        uint4 u = p4[t + 256 * i];
        uint32_t ws[4] = {u.x, u.y, u.z, u.w};
        #pragma unroll
        for (int j = 0; j < 4; j++) {
            float2 f = __half22float2(*(const __half2*)&ws[j]);
            s  += f.x + f.y;
            sq += f.x * f.x + f.y * f.y;
        }
    }
    #pragma unroll
    for (int off = 16; off; off >>= 1) {
        s  += __shfl_xor_sync(0xffffffffu, s,  off);
        sq += __shfl_xor_sync(0xffffffffu, sq, off);
    }
    if ((t & 31) == 0) { red[t >> 5] = s; red[8 + (t >> 5)] = sq; }
    __syncthreads();
    if (t == 0) {
        float S = 0.f, Q = 0.f;
        #pragma unroll
        for (int i = 0; i < 8; i++) { S += red[i]; Q += red[8 + i]; }
        float mean = S * (1.f / HWN);
        float var  = Q * (1.f / HWN) - mean * mean;
        g_mu[row] = mean;
        g_rs[row] = rsqrtf(var + EPSI);
    }
}

// ---------------------------------------------------------------------------
// Normalize + transpose K (fp16 in) -> g_kh [b,h][n][dk] fp16
// ---------------------------------------------------------------------------
__global__ __launch_bounds__(256) void convert_k_kernel()
{
    __shared__ float tile[32][132];
    const int b = blockIdx.z, h = blockIdx.y, n0 = blockIdx.x << 7;
    const int t = threadIdx.x;
    {
        const int dk = t >> 3, seg = (t & 7) << 4;
        const int row = b * CKD + h * DK + dk;
        const float mu = g_mu[row], rs = g_rs[row];
        const __half* src = g_k16 + (size_t)row * HWN + n0 + seg;
        #pragma unroll
        for (int u = 0; u < 2; u++) {
            uint4 v = ((const uint4*)src)[u];
            uint32_t ws[4] = {v.x, v.y, v.z, v.w};
            #pragma unroll
            for (int j = 0; j < 4; j++) {
                float2 f = __half22float2(*(const __half2*)&ws[j]);
                tile[dk][seg + (u << 3) + 2*j]     = (f.x - mu) * rs;
                tile[dk][seg + (u << 3) + 2*j + 1] = (f.y - mu) * rs;
            }
        }
    }
    __syncthreads();
    const int n = t >> 1, part = t & 1;
    uint32_t w[8];
    #pragma unroll
    for (int j = 0; j < 8; j++)
        w[j] = h2pack(tile[part*16 + 2*j][n], tile[part*16 + 2*j + 1][n]);
    __half* dst = g_kh + ((size_t)(b * NH + h) * HWN + n0 + n) * DK + part * 16;
    ((uint4*)dst)[0] = make_uint4(w[0], w[1], w[2], w[3]);
    ((uint4*)dst)[1] = make_uint4(w[4], w[5], w[6], w[7]);
}

// ---------------------------------------------------------------------------
// HMMA attention: 64 q-rows/block, 128 threads (4 warps), 3-stage cp.async.
// grid (NL/64, NH, BATCH) = 512 blocks.
// ---------------------------------------------------------------------------
__global__ __launch_bounds__(128) void attn_hmma_kernel()
{
    __shared__ __align__(16) __half qs_h[64 * 32];        // 4 KB
    __shared__ __align__(16) __half kb[3][64 * 32];       // 3 x 4 KB
    __shared__ __align__(16) __half vb[3][32 * 64];       // 3 x 4 KB

    const int b = blockIdx.z, h = blockIdx.y, l0 = blockIdx.x << 6;
    const int t = threadIdx.x, w = t >> 5, lane = t & 31;
    const int g = lane >> 2, l = lane & 3;

    {   // stage Q: 64 rows, 2 uint4/thread
        const int row = t >> 1, cp = (t & 1) << 1;
        const uint4* srch = (const uint4*)(g_qh + (size_t)(b * NL + l0 + row) * CKD + h * DK);
        const int sw = (row >> 1) & 3;
        ((uint4*)qs_h)[row * 4 + (cp ^ sw)]       = srch[cp];
        ((uint4*)qs_h)[row * 4 + ((cp + 1) ^ sw)] = srch[cp + 1];
    }

    const __half* kg = g_kh + (size_t)(b * NH + h) * HWN * DK;
    const __half* vg = g_vh + ((size_t)b * CKD + h * DV) * HWN;
    const uint4* kg4 = (const uint4*)kg;
    const uint4* vg4 = (const uint4*)vg;

    // K: 64 rows x 4 uint4; thread covers 2: krow = t>>1, chunks kc2, kc2+1
    const int krow = t >> 1, kc2 = (t & 1) << 1;
    const int ksw = (krow >> 1) & 3;
    const uint32_t kd0 = (uint32_t)(krow * 4 + (kc2 ^ ksw)) * 16;
    const uint32_t kd1 = (uint32_t)(krow * 4 + ((kc2 + 1) ^ ksw)) * 16;
    // V: 32 rows x 8 uint4; thread covers 2: vrow = t>>2, chunks vc2, vc2+1
    const int vrow = t >> 2, vc2 = (t & 3) << 1;
    const int vsw = vrow & 7;
    const uint32_t vd0 = (uint32_t)(vrow * 8 + (vc2 ^ vsw)) * 16;
    const uint32_t vd1 = (uint32_t)(vrow * 8 + ((vc2 + 1) ^ vsw)) * 16;

    uint32_t kbB[3], vbB[3];
    #pragma unroll
    for (int p = 0; p < 3; p++) {
        kbB[p] = smem_u32(kb[p]);
        vbB[p] = smem_u32(vb[p]);
    }

    #pragma unroll
    for (int p = 0; p < 2; p++) {
        cpa16(kbB[p] + kd0, kg4 + (p * 64 + krow) * 4 + kc2);
        cpa16(kbB[p] + kd1, kg4 + (p * 64 + krow) * 4 + kc2 + 1);
        cpa16(vbB[p] + vd0, vg4 + (size_t)vrow * (HWN / 8) + p * 8 + vc2);
        cpa16(vbB[p] + vd1, vg4 + (size_t)vrow * (HWN / 8) + p * 8 + vc2 + 1);
        CP_COMMIT();
    }
    __syncthreads();                     // qs_h visible

    uint32_t Ah[2][4];
    {
        const int row = (w << 4) + (lane & 7) + ((lane >> 3) & 1) * 8;
        const int kc  = lane >> 4;
        const int sw  = (row >> 1) & 3;
        #pragma unroll
        for (int s = 0; s < 2; s++) {
            const uint32_t off = (row * 4 + (((s << 1) + kc) ^ sw)) * 16;
            ldsm4(Ah[s], smem_u32(qs_h) + off);
        }
    }

    float O[4][4] = {};
    float ps0 = 0.f, ps1 = 0.f;
    int stage = 0;

    for (int c = 0; c < 64; c++) {
        if (c == 63) { CP_WAIT0(); } else { CP_WAIT1(); }
        __syncthreads();
        if (c < 62) {
            const int nx = (stage + 2 >= 3) ? stage - 1 : stage + 2;
            cpa16(kbB[nx] + kd0, kg4 + ((c + 2) * 64 + krow) * 4 + kc2);
            cpa16(kbB[nx] + kd1, kg4 + ((c + 2) * 64 + krow) * 4 + kc2 + 1);
            cpa16(vbB[nx] + vd0, vg4 + (size_t)vrow * (HWN / 8) + (c + 2) * 8 + vc2);
            cpa16(vbB[nx] + vd1, vg4 + (size_t)vrow * (HWN / 8) + (c + 2) * 8 + vc2 + 1);
            CP_COMMIT();
        }
        const uint32_t ksb = kbB[stage], vsb = vbB[stage];

        float S[8][4];
        #pragma unroll
        for (int j = 0; j < 8; j++) { S[j][0]=0.f; S[j][1]=0.f; S[j][2]=0.f; S[j][3]=0.f; }
        #pragma unroll
        for (int j = 0; j < 8; j++) {
            const int row = (j << 3) + (lane & 7);
            uint32_t bk_[4];
            ldsm4(bk_, ksb + (row * 4 + ((lane >> 3) ^ ((row >> 1) & 3))) * 16);
            mma16816(S[j], Ah[0], bk_[0], bk_[1]);
            mma16816(S[j], Ah[1], bk_[2], bk_[3]);
        }

        uint32_t Ph[4][4];
        #pragma unroll
        for (int j = 0; j < 8; j++) {
            float p0 = ex2(S[j][0]), p1 = ex2(S[j][1]);
            float p2 = ex2(S[j][2]), p3 = ex2(S[j][3]);
            ps0 += p0 + p1;
            ps1 += p2 + p3;
            Ph[j >> 1][(j & 1) * 2 + 0] = h2pack(p0, p1);
            Ph[j >> 1][(j & 1) * 2 + 1] = h2pack(p2, p3);
        }

        #pragma unroll
        for (int j = 0; j < 4; j++) {
            #pragma unroll
            for (int s2 = 0; s2 < 2; s2++) {
                const int row = (j << 3) + (lane & 7);
                uint32_t bv_[4];
                ldsm4(bv_, vsb + (row * 8 + (((s2 << 2) + (lane >> 3)) ^ (row & 7))) * 16);
                mma16816(O[j], Ph[2 * s2],     bv_[0], bv_[1]);
                mma16816(O[j], Ph[2 * s2 + 1], bv_[2], bv_[3]);
            }
        }
        stage = (stage + 1 == 3) ? 0 : stage + 1;
    }

    ps0 += __shfl_xor_sync(0xffffffffu, ps0, 1);
    ps0 += __shfl_xor_sync(0xffffffffu, ps0, 2);
    ps1 += __shfl_xor_sync(0xffffffffu, ps1, 1);
    ps1 += __shfl_xor_sync(0xffffffffu, ps1, 2);
    const float inv0 = 1.0f / ps0, inv1 = 1.0f / ps1;

    const int r0 = l0 + (w << 4) + g;
    const size_t i0 = (size_t)(b * NL + r0) * CKD + h * DV + (l << 1);
    const size_t i1 = i0 + (size_t)8 * CKD;
    #pragma unroll
    for (int j = 0; j < 4; j++) {
        float a0 = O[j][0] * inv0, a1 = O[j][1] * inv0;
        float b0 = O[j][2] * inv1, b1 = O[j][3] * inv1;
        __half h0 = __float2half_rn(a0), h1 = __float2half_rn(a1);
        __half h2 = __float2half_rn(b0), h3 = __float2half_rn(b1);
        *(uint32_t*)&g_ath[i0 + (j << 3)] = h2pack(__half2float(h0), __half2float(h1));
        *(uint32_t*)&g_atl[i0 + (j << 3)] = h2pack(a0 - __half2float(h0), a1 - __half2float(h1));
        *(uint32_t*)&g_ath[i1 + (j << 3)] = h2pack(__half2float(h2), __half2float(h3));
        *(uint32_t*)&g_atl[i1 + (j << 3)] = h2pack(b0 - __half2float(h2), b1 - __half2float(h3));
    }
}

// ---------------------------------------------------------------------------
// InstanceNorm over Nl on g_y + transposed write out[b,l,o]
// ---------------------------------------------------------------------------
__global__ __launch_bounds__(256) void norm_t_kernel(float* __restrict__ out)
{
    __shared__ float tile[32][33];
    __shared__ float meanv[32], rstdv[32];
    const int b = blockIdx.y, o0 = blockIdx.x << 5;
    const int t = threadIdx.x, lane = t & 31, w = t >> 5;

    #pragma unroll
    for (int j = 0; j < 4; j++) {
        const int ol = (w << 2) + j;
        const float* yp = g_y + (size_t)(o0 + ol) * MTOT + b * NL;
        float s = 0.f, sq = 0.f;
        #pragma unroll
        for (int i = 0; i < 8; i++) {
            float4 v = *(const float4*)&yp[(i * 32 + lane) * 4];
            s  += v.x + v.y + v.z + v.w;
            sq += v.x*v.x + v.y*v.y + v.z*v.z + v.w*v.w;
        }
        #pragma unroll
        for (int off = 16; off; off >>= 1) {
            s  += __shfl_xor_sync(0xffffffffu, s,  off);
            sq += __shfl_xor_sync(0xffffffffu, sq, off);
        }
        if (lane == 0) {
            float mean = s * (1.f / NL);
            float var  = sq * (1.f / NL) - mean * mean;
            meanv[ol] = mean;
            rstdv[ol] = rsqrtf(var + EPSI);
        }
    }
    __syncthreads();
    const float mo = meanv[lane], ro = rstdv[lane];
    for (int l0 = 0; l0 < NL; l0 += 32) {
        __syncthreads();
        #pragma unroll
        for (int j = 0; j < 4; j++)
            tile[w + 8*j][lane] =
                g_y[(size_t)(o0 + w + 8*j) * MTOT + b * NL + l0 + lane];
        __syncthreads();
        #pragma unroll
        for (int j = 0; j < 4; j++)
            out[(size_t)(b * NL + l0 + w + 8*j) * CKD + o0 + lane] =
                (tile[lane][w + 8*j] - mo) * ro;
    }
}

// ---------------------------------------------------------------------------
extern "C" void kernel_launch(void* const* d_in, const int* in_sizes, int n_in,
                              void* d_out, int out_size)
{
    const float* l  = (const float*)d_in[0];
    const float* x  = (const float*)d_in[1];
    const float* Wq = (const float*)d_in[2];
    const float* bq = (const float*)d_in[3];
    const float* Wk = (const float*)d_in[4];
    const float* Wv = (const float*)d_in[6];
    const float* bv = (const float*)d_in[7];
    const float* Ww = (const float*)d_in[8];
    float* out = (float*)d_out;

    cudaFuncSetAttribute(gemm_q_hmma,
                         cudaFuncAttributeMaxDynamicSharedMemorySize, KV_SMEM);
    cudaFuncSetAttribute(gemm_kv_hmma,
                         cudaFuncAttributeMaxDynamicSharedMemorySize, KV_SMEM);
    cudaFuncSetAttribute(gemm_proj_hmma,
                         cudaFuncAttributeMaxDynamicSharedMemorySize, KV_SMEM);

    split_w_kernel    <<<512, 256>>>(Wk, Wv);
    split_wq_kernel   <<<CKD, 256>>>(Wq);
    split_ww_kernel   <<<CKD, 128>>>(Ww);
    split_xl_kernel   <<<XBLOCKS + LBLOCKS, 256>>>(x, l);
    gemm_q_hmma       <<<dim3(MTOT / 128, CKD / 64), 256, KV_SMEM>>>(bq);
    gemm_kv_hmma      <<<dim3(HWN / 128, 8, BATCH), 256, KV_SMEM>>>(bv);
    inorm_stats_kernel<<<BATCH * CKD, 256>>>();
    convert_k_kernel  <<<dim3(HWN / 128, NH, BATCH), 256>>>();
    attn_hmma_kernel  <<<dim3(NL / 64, NH, BATCH), 128>>>();
    gemm_proj_hmma    <<<dim3(MTOT / 128, CKD / 64), 256, KV_SMEM>>>();
    norm_t_kernel     <<<dim3(CKD / 32, BATCH), 256>>>(out);
}

// round 16
// speedup vs baseline: 1.2489x; 1.2489x over previous
#include <cuda_runtime.h>
#include <cuda_fp16.h>
#include <cstdint>

#define BATCH 4
#define NL    1024
#define HWN   4096
#define CIN   512
#define CKD   256
#define NH    8
#define DK    32
#define DV    32
#define MTOT  4096
#define EPSI  1e-5f
#define QSCALE 0.09016844f   /* (1/16) * log2(e) */
#define S1_SMEM (3 * 12288)  /* 3 stages x (xh 8K + wh 4K) single-term */
#define S2_SMEM (3 * 20480)  /* 3 stages x (ah 8K + al 8K + wh 4K) 2-term */

typedef unsigned long long u64;

// ---------------- helpers ----------------
__device__ __forceinline__ float ex2(float x) {
    float r; asm("ex2.approx.f32 %0, %1;" : "=f"(r) : "f"(x)); return r;
}
__device__ __forceinline__ uint32_t h2pack(float lo, float hi) {
    __half2 h = __floats2half2_rn(lo, hi);     // .x = lo half
    return *(uint32_t*)&h;
}
__device__ __forceinline__ uint32_t smem_u32(const void* p) {
    uint32_t a;
    asm("{ .reg .u64 t; cvta.to.shared.u64 t, %1; cvt.u32.u64 %0, t; }"
        : "=r"(a) : "l"(p));
    return a;
}
__device__ __forceinline__ void ldsm4(uint32_t* r, uint32_t addr) {
    asm volatile("ldmatrix.sync.aligned.m8n8.x4.shared.b16 {%0,%1,%2,%3}, [%4];"
        : "=r"(r[0]), "=r"(r[1]), "=r"(r[2]), "=r"(r[3]) : "r"(addr));
}
__device__ __forceinline__ void mma16816(float* c, const uint32_t* a,
                                         const uint32_t b0, const uint32_t b1) {
    asm volatile(
        "mma.sync.aligned.m16n8k16.row.col.f32.f16.f16.f32 "
        "{%0,%1,%2,%3},{%4,%5,%6,%7},{%8,%9},{%0,%1,%2,%3};"
        : "+f"(c[0]), "+f"(c[1]), "+f"(c[2]), "+f"(c[3])
        : "r"(a[0]), "r"(a[1]), "r"(a[2]), "r"(a[3]), "r"(b0), "r"(b1));
}
__device__ __forceinline__ void cpa16(uint32_t dst, const void* src) {
    asm volatile("cp.async.cg.shared.global [%0], [%1], 16;"
        :: "r"(dst), "l"(src) : "memory");
}
#define CP_COMMIT() asm volatile("cp.async.commit_group;" ::: "memory")
#define CP_WAIT0()  asm volatile("cp.async.wait_group 0;" ::: "memory")
#define CP_WAIT1()  asm volatile("cp.async.wait_group 1;" ::: "memory")

// ---------------- scratch ----------------
__device__ __half g_qh[MTOT * CKD];                       // q fp16, prescaled
__device__ __half g_lh[MTOT * CIN];                       // l fp16
__device__ __half g_wqh[CKD * CIN];                       // Wq fp16
__device__ __half g_xh[(size_t)BATCH * HWN * CIN];        // x fp16
__device__ __half g_wh[512 * CIN];                        // [Wk;Wv] fp16
__device__ __half g_wwh[CKD * CKD];                       // Ww fp16
__device__ __half g_k16[(size_t)BATCH * CKD * HWN];       // fp16 [b,c,n] (pre-norm)
__device__ float  g_mu[BATCH * CKD];                      // K row mean
__device__ float  g_rs[BATCH * CKD];                      // K row rstd
__device__ __half g_kh[(size_t)BATCH * NH * HWN * DK];    // [b,h][n][dk] normalized
__device__ __half g_vh[(size_t)BATCH * CKD * HWN];        // [b,c,n]
__device__ __half g_ath[MTOT * CKD];                      // attention out hi
__device__ __half g_atl[MTOT * CKD];                      // attention out lo
__device__ float  g_y[CKD * MTOT];

#define XBLOCKS ((BATCH * HWN * CIN) / (256 * 8))   /* 4096 */
#define LBLOCKS ((MTOT * CIN) / (256 * 8))          /* 1024 */

// ---------------------------------------------------------------------------
// combined cast of x and l -> fp16 (hi only)
// ---------------------------------------------------------------------------
__global__ __launch_bounds__(256) void split_xl_kernel(
    const float* __restrict__ X, const float* __restrict__ L)
{
    const bool isl = blockIdx.x >= XBLOCKS;
    const int blk = isl ? blockIdx.x - XBLOCKS : blockIdx.x;
    const float* src = isl ? L : X;
    __half* dh = isl ? g_lh : g_xh;
    const size_t i0 = ((size_t)blk * 256 + threadIdx.x) * 8;
    float4 f0 = *(const float4*)(src + i0);
    float4 f1 = *(const float4*)(src + i0 + 4);
    *(uint2*)(dh + i0)     = make_uint2(h2pack(f0.x, f0.y), h2pack(f0.z, f0.w));
    *(uint2*)(dh + i0 + 4) = make_uint2(h2pack(f1.x, f1.y), h2pack(f1.z, f1.w));
}

// ---------------------------------------------------------------------------
// weight casts -> fp16
// ---------------------------------------------------------------------------
__global__ __launch_bounds__(256) void split_w_kernel(
    const float* __restrict__ Wk, const float* __restrict__ Wv)
{
    const int row = blockIdx.x;
    const float* src = (row < CKD) ? (Wk + (size_t)row * CIN)
                                   : (Wv + (size_t)(row - CKD) * CIN);
    const int c = threadIdx.x * 2;
    *(uint32_t*)(g_wh + (size_t)row * CIN + c) = h2pack(src[c], src[c + 1]);
}
__global__ __launch_bounds__(256) void split_wq_kernel(const float* __restrict__ Wq)
{
    const int row = blockIdx.x;
    const int c = threadIdx.x * 2;
    *(uint32_t*)(g_wqh + (size_t)row * CIN + c) =
        h2pack(Wq[(size_t)row * CIN + c], Wq[(size_t)row * CIN + c + 1]);
}
__global__ __launch_bounds__(128) void split_ww_kernel(const float* __restrict__ Ww)
{
    const int row = blockIdx.x;
    const int c = threadIdx.x * 2;
    *(uint32_t*)(g_wwh + (size_t)row * CKD + c) =
        h2pack(Ww[(size_t)row * CKD + c], Ww[(size_t)row * CKD + c + 1]);
}

// ---------------------------------------------------------------------------
// HMMA q GEMM (single-term): g_qh[m][ck] = (l.Wq + bq)*QSCALE
// grid (MTOT/128, CKD/64), 3-stage cp.async, K=512 (16 ksteps)
// ---------------------------------------------------------------------------
__global__ void __launch_bounds__(256) gemm_q_hmma(const float* __restrict__ bq)
{
    extern __shared__ __align__(16) char dynsm[];
    const int c0 = blockIdx.y << 6;
    const int m0 = blockIdx.x << 7;
    const int t = threadIdx.x, w = t >> 5, lane = t & 31;

    const int xrow = t >> 1, xc2 = (t & 1) << 1;
    const int wrow = t >> 2, wc = t & 3;
    const uint4* pxh = (const uint4*)(g_lh + (size_t)(m0 + xrow) * CIN);
    const uint4* pwh = (const uint4*)(g_wqh + (size_t)(c0 + wrow) * CIN);

    const int xsw = (xrow >> 1) & 3, wsw = (wrow >> 1) & 3;
    const uint32_t xd0 = (uint32_t)(xrow * 4 + ((xc2)     ^ xsw)) * 16;
    const uint32_t xd1 = (uint32_t)(xrow * 4 + ((xc2 + 1) ^ xsw)) * 16;
    const uint32_t wd  = (uint32_t)(wrow * 4 + (wc ^ wsw)) * 16;

    const uint32_t base = smem_u32(dynsm);
    uint32_t xhB[3], whB[3];
    #pragma unroll
    for (int p = 0; p < 3; p++) {
        xhB[p] = base + p * 12288;
        whB[p] = xhB[p] + 8192;
    }

    const int cw = (w & 3) << 4;
    const int nw = (w >> 2) << 6;

    #pragma unroll
    for (int p = 0; p < 2; p++) {
        const int kc = p << 2;
        cpa16(xhB[p] + xd0, pxh + kc + xc2);
        cpa16(xhB[p] + xd1, pxh + kc + xc2 + 1);
        cpa16(whB[p] + wd,  pwh + kc + wc);
        CP_COMMIT();
    }

    float C[8][4] = {};
    int stage = 0;

    for (int s = 0; s < 16; s++) {
        if (s == 15) { CP_WAIT0(); } else { CP_WAIT1(); }
        __syncthreads();
        if (s < 14) {
            const int kc = (s + 2) << 2;
            const int nx = (stage + 2 >= 3) ? stage - 1 : stage + 2;
            cpa16(xhB[nx] + xd0, pxh + kc + xc2);
            cpa16(xhB[nx] + xd1, pxh + kc + xc2 + 1);
            cpa16(whB[nx] + wd,  pwh + kc + wc);
            CP_COMMIT();
        }

        uint32_t Ah[2][4];
        const int arow = cw + (lane & 7) + ((lane >> 3) & 1) * 8;
        const int aswz = (arow >> 1) & 3;
        #pragma unroll
        for (int ks = 0; ks < 2; ks++) {
            const uint32_t aoff = (arow * 4 + (((ks << 1) + (lane >> 4)) ^ aswz)) * 16;
            ldsm4(Ah[ks], whB[stage] + aoff);
        }
        #pragma unroll
        for (int j = 0; j < 8; j++) {
            const int brow = nw + (j << 3) + (lane & 7);
            const uint32_t boff = (brow * 4 + ((lane >> 3) ^ ((brow >> 1) & 3))) * 16;
            uint32_t bh[4];
            ldsm4(bh, xhB[stage] + boff);
            mma16816(C[j], Ah[0], bh[0], bh[1]);
            mma16816(C[j], Ah[1], bh[2], bh[3]);
        }
        stage = (stage + 1 == 3) ? 0 : stage + 1;
    }

    const int g = lane >> 2, l = lane & 3;
    const int cc = c0 + cw + g;
    const float b0 = bq[cc], b1 = bq[cc + 8];
    #pragma unroll
    for (int j = 0; j < 8; j++) {
        const int m = m0 + nw + (j << 3) + (l << 1);
        g_qh[(size_t)m * CKD + cc]           = __float2half_rn((C[j][0] + b0) * QSCALE);
        g_qh[(size_t)(m + 1) * CKD + cc]     = __float2half_rn((C[j][1] + b0) * QSCALE);
        g_qh[(size_t)m * CKD + cc + 8]       = __float2half_rn((C[j][2] + b1) * QSCALE);
        g_qh[(size_t)(m + 1) * CKD + cc + 8] = __float2half_rn((C[j][3] + b1) * QSCALE);
    }
}

// ---------------------------------------------------------------------------
// HMMA k/v GEMM (single-term), 3-stage cp.async.
// ---------------------------------------------------------------------------
__global__ void __launch_bounds__(256) gemm_kv_hmma(const float* __restrict__ bv)
{
    extern __shared__ __align__(16) char dynsm[];
    const int bat = blockIdx.z;
    const int c0  = blockIdx.y << 6;
    const int n0  = blockIdx.x << 7;
    const int t = threadIdx.x, w = t >> 5, lane = t & 31;

    const int xrow = t >> 1, xc2 = (t & 1) << 1;
    const int wrow = t >> 2, wc = t & 3;
    const uint4* pxh = (const uint4*)(g_xh + (size_t)(bat * HWN + n0 + xrow) * CIN);
    const uint4* pwh = (const uint4*)(g_wh + (size_t)(c0 + wrow) * CIN);

    const int xsw = (xrow >> 1) & 3, wsw = (wrow >> 1) & 3;
    const uint32_t xd0 = (uint32_t)(xrow * 4 + ((xc2)     ^ xsw)) * 16;
    const uint32_t xd1 = (uint32_t)(xrow * 4 + ((xc2 + 1) ^ xsw)) * 16;
    const uint32_t wd  = (uint32_t)(wrow * 4 + (wc ^ wsw)) * 16;

    const uint32_t base = smem_u32(dynsm);
    uint32_t xhB[3], whB[3];
    #pragma unroll
    for (int p = 0; p < 3; p++) {
        xhB[p] = base + p * 12288;
        whB[p] = xhB[p] + 8192;
    }

    const int cw = (w & 3) << 4;
    const int nw = (w >> 2) << 6;

    #pragma unroll
    for (int p = 0; p < 2; p++) {
        const int kc = p << 2;
        cpa16(xhB[p] + xd0, pxh + kc + xc2);
        cpa16(xhB[p] + xd1, pxh + kc + xc2 + 1);
        cpa16(whB[p] + wd,  pwh + kc + wc);
        CP_COMMIT();
    }

    float C[8][4] = {};
    int stage = 0;

    for (int s = 0; s < 16; s++) {
        if (s == 15) { CP_WAIT0(); } else { CP_WAIT1(); }
        __syncthreads();
        if (s < 14) {
            const int kc = (s + 2) << 2;
            const int nx = (stage + 2 >= 3) ? stage - 1 : stage + 2;
            cpa16(xhB[nx] + xd0, pxh + kc + xc2);
            cpa16(xhB[nx] + xd1, pxh + kc + xc2 + 1);
            cpa16(whB[nx] + wd,  pwh + kc + wc);
            CP_COMMIT();
        }

        uint32_t Ah[2][4];
        const int arow = cw + (lane & 7) + ((lane >> 3) & 1) * 8;
        const int aswz = (arow >> 1) & 3;
        #pragma unroll
        for (int ks = 0; ks < 2; ks++) {
            const uint32_t aoff = (arow * 4 + (((ks << 1) + (lane >> 4)) ^ aswz)) * 16;
            ldsm4(Ah[ks], whB[stage] + aoff);
        }
        #pragma unroll
        for (int j = 0; j < 8; j++) {
            const int brow = nw + (j << 3) + (lane & 7);
            const uint32_t boff = (brow * 4 + ((lane >> 3) ^ ((brow >> 1) & 3))) * 16;
            uint32_t bh[4];
            ldsm4(bh, xhB[stage] + boff);
            mma16816(C[j], Ah[0], bh[0], bh[1]);
            mma16816(C[j], Ah[1], bh[2], bh[3]);
        }
        stage = (stage + 1 == 3) ? 0 : stage + 1;
    }

    const int g = lane >> 2, l = lane & 3;
    const int cc = c0 + cw + g;
    if (c0 < CKD) {
        __half* k0p = g_k16 + ((size_t)bat * CKD + cc) * HWN;
        __half* k1p = g_k16 + ((size_t)bat * CKD + cc + 8) * HWN;
        #pragma unroll
        for (int j = 0; j < 8; j++) {
            const int n = n0 + nw + (j << 3) + (l << 1);
            *(uint32_t*)(k0p + n) = h2pack(C[j][0], C[j][1]);
            *(uint32_t*)(k1p + n) = h2pack(C[j][2], C[j][3]);
        }
    } else {
        const int cv = cc - CKD;
        const float b0 = bv[cv], b1 = bv[cv + 8];
        __half* v0p = g_vh + ((size_t)bat * CKD + cv) * HWN;
        __half* v1p = g_vh + ((size_t)bat * CKD + cv + 8) * HWN;
        #pragma unroll
        for (int j = 0; j < 8; j++) {
            const int n = n0 + nw + (j << 3) + (l << 1);
            *(uint32_t*)(v0p + n) = h2pack(C[j][0] + b0, C[j][1] + b0);
            *(uint32_t*)(v1p + n) = h2pack(C[j][2] + b1, C[j][3] + b1);
        }
    }
}

// ---------------------------------------------------------------------------
// HMMA projection GEMM (2-term, att hi/lo): g_y[o][m] = att[m][:] . Ww[o][:]
// ---------------------------------------------------------------------------
__global__ void __launch_bounds__(256) gemm_proj_hmma()
{
    extern __shared__ __align__(16) char dynsm[];
    const int c0 = blockIdx.y << 6;
    const int m0 = blockIdx.x << 7;
    const int t = threadIdx.x, w = t >> 5, lane = t & 31;

    const int xrow = t >> 1, xc2 = (t & 1) << 1;
    const int wrow = t >> 2, wc = t & 3;
    const uint4* pxh = (const uint4*)(g_ath + (size_t)(m0 + xrow) * CKD);
    const uint4* pxl = (const uint4*)(g_atl + (size_t)(m0 + xrow) * CKD);
    const uint4* pwh = (const uint4*)(g_wwh + (size_t)(c0 + wrow) * CKD);

    const int xsw = (xrow >> 1) & 3, wsw = (wrow >> 1) & 3;
    const uint32_t xd0 = (uint32_t)(xrow * 4 + ((xc2)     ^ xsw)) * 16;
    const uint32_t xd1 = (uint32_t)(xrow * 4 + ((xc2 + 1) ^ xsw)) * 16;
    const uint32_t wd  = (uint32_t)(wrow * 4 + (wc ^ wsw)) * 16;

    const uint32_t base = smem_u32(dynsm);
    uint32_t xhB[3], xlB[3], whB[3];
    #pragma unroll
    for (int p = 0; p < 3; p++) {
        xhB[p] = base + p * 20480;
        xlB[p] = xhB[p] + 8192;
        whB[p] = xhB[p] + 16384;
    }

    const int cw = (w & 3) << 4;
    const int nw = (w >> 2) << 6;

    #pragma unroll
    for (int p = 0; p < 2; p++) {
        const int kc = p << 2;
        cpa16(xhB[p] + xd0, pxh + kc + xc2);
        cpa16(xhB[p] + xd1, pxh + kc + xc2 + 1);
        cpa16(xlB[p] + xd0, pxl + kc + xc2);
        cpa16(xlB[p] + xd1, pxl + kc + xc2 + 1);
        cpa16(whB[p] + wd,  pwh + kc + wc);
        CP_COMMIT();
    }

    float C[8][4] = {};
    int stage = 0;

    for (int s = 0; s < 8; s++) {
        if (s == 7) { CP_WAIT0(); } else { CP_WAIT1(); }
        __syncthreads();
        if (s < 6) {
            const int kc = (s + 2) << 2;
            const int nx = (stage + 2 >= 3) ? stage - 1 : stage + 2;
            cpa16(xhB[nx] + xd0, pxh + kc + xc2);
            cpa16(xhB[nx] + xd1, pxh + kc + xc2 + 1);
            cpa16(xlB[nx] + xd0, pxl + kc + xc2);
            cpa16(xlB[nx] + xd1, pxl + kc + xc2 + 1);
            cpa16(whB[nx] + wd,  pwh + kc + wc);
            CP_COMMIT();
        }

        uint32_t Ah[2][4];
        const int arow = cw + (lane & 7) + ((lane >> 3) & 1) * 8;
        const int aswz = (arow >> 1) & 3;
        #pragma unroll
        for (int ks = 0; ks < 2; ks++) {
            const uint32_t aoff = (arow * 4 + (((ks << 1) + (lane >> 4)) ^ aswz)) * 16;
            ldsm4(Ah[ks], whB[stage] + aoff);
        }
        #pragma unroll
        for (int j = 0; j < 8; j++) {
            const int brow = nw + (j << 3) + (lane & 7);
            const uint32_t boff = (brow * 4 + ((lane >> 3) ^ ((brow >> 1) & 3))) * 16;
            uint32_t bh[4], bl[4];
            ldsm4(bh, xhB[stage] + boff);
            ldsm4(bl, xlB[stage] + boff);
            mma16816(C[j], Ah[0], bh[0], bh[1]);
            mma16816(C[j], Ah[1], bh[2], bh[3]);
            mma16816(C[j], Ah[0], bl[0], bl[1]);
            mma16816(C[j], Ah[1], bl[2], bl[3]);
        }
        stage = (stage + 1 == 3) ? 0 : stage + 1;
    }

    const int g = lane >> 2, l = lane & 3;
    const int cc = c0 + cw + g;
    float* y0 = g_y + (size_t)cc * MTOT;
    float* y1 = g_y + (size_t)(cc + 8) * MTOT;
    #pragma unroll
    for (int j = 0; j < 8; j++) {
        const int m = m0 + nw + (j << 3) + (l << 1);
        *(float2*)(y0 + m) = make_float2(C[j][0], C[j][1]);
        *(float2*)(y1 + m) = make_float2(C[j][2], C[j][3]);
    }
}

// ---------------------------------------------------------------------------
// K InstanceNorm stats (fp16 input, fp32 accumulate)
// ---------------------------------------------------------------------------
__global__ __launch_bounds__(256) void inorm_stats_kernel()
{
    __shared__ float red[16];
    const int row = blockIdx.x;
    const uint4* p4 = reinterpret_cast<const uint4*>(g_k16 + (size_t)row * HWN);
    const int t = threadIdx.x;
    float s = 0.f, sq = 0.f;
    #pragma unroll
    for (int i = 0; i < 2; i++) {
        uint4 u = p4[t + 256 * i];
        uint32_t ws[4] = {u.x, u.y, u.z, u.w};
        #pragma unroll
        for (int j = 0; j < 4; j++) {
            float2 f = __half22float2(*(const __half2*)&ws[j]);
            s  += f.x + f.y;
            sq += f.x * f.x + f.y * f.y;
        }
    }
    #pragma unroll
    for (int off = 16; off; off >>= 1) {
        s  += __shfl_xor_sync(0xffffffffu, s,  off);
        sq += __shfl_xor_sync(0xffffffffu, sq, off);
    }
    if ((t & 31) == 0) { red[t >> 5] = s; red[8 + (t >> 5)] = sq; }
    __syncthreads();
    if (t == 0) {
        float S = 0.f, Q = 0.f;
        #pragma unroll
        for (int i = 0; i < 8; i++) { S += red[i]; Q += red[8 + i]; }
        float mean = S * (1.f / HWN);
        float var  = Q * (1.f / HWN) - mean * mean;
        g_mu[row] = mean;
        g_rs[row] = rsqrtf(var + EPSI);
    }
}

// ---------------------------------------------------------------------------
// Normalize + transpose K (fp16 in) -> g_kh [b,h][n][dk] fp16
// ---------------------------------------------------------------------------
__global__ __launch_bounds__(256) void convert_k_kernel()
{
    __shared__ float tile[32][132];
    const int b = blockIdx.z, h = blockIdx.y, n0 = blockIdx.x << 7;
    const int t = threadIdx.x;
    {
        const int dk = t >> 3, seg = (t & 7) << 4;
        const int row = b * CKD + h * DK + dk;
        const float mu = g_mu[row], rs = g_rs[row];
        const __half* src = g_k16 + (size_t)row * HWN + n0 + seg;
        #pragma unroll
        for (int u = 0; u < 2; u++) {
            uint4 v = ((const uint4*)src)[u];
            uint32_t ws[4] = {v.x, v.y, v.z, v.w};
            #pragma unroll
            for (int j = 0; j < 4; j++) {
                float2 f = __half22float2(*(const __half2*)&ws[j]);
                tile[dk][seg + (u << 3) + 2*j]     = (f.x - mu) * rs;
                tile[dk][seg + (u << 3) + 2*j + 1] = (f.y - mu) * rs;
            }
        }
    }
    __syncthreads();
    const int n = t >> 1, part = t & 1;
    uint32_t w[8];
    #pragma unroll
    for (int j = 0; j < 8; j++)
        w[j] = h2pack(tile[part*16 + 2*j][n], tile[part*16 + 2*j + 1][n]);
    __half* dst = g_kh + ((size_t)(b * NH + h) * HWN + n0 + n) * DK + part * 16;
    ((uint4*)dst)[0] = make_uint4(w[0], w[1], w[2], w[3]);
    ((uint4*)dst)[1] = make_uint4(w[4], w[5], w[6], w[7]);
}

// ---------------------------------------------------------------------------
// HMMA attention (R14 variant: 128 rows, 256 threads, 3-stage cp.async)
// ---------------------------------------------------------------------------
__global__ __launch_bounds__(256) void attn_hmma_kernel()
{
    __shared__ __align__(16) __half qs_h[128 * 32];       // 8 KB
    __shared__ __align__(16) __half kb[3][64 * 32];       // 3 x 4 KB
    __shared__ __align__(16) __half vb[3][32 * 64];       // 3 x 4 KB

    const int b = blockIdx.z, h = blockIdx.y, l0 = blockIdx.x << 7;
    const int t = threadIdx.x, w = t >> 5, lane = t & 31;
    const int g = lane >> 2, l = lane & 3;

    {   // stage Q
        const int row = t >> 1, cp = (t & 1) << 1;
        const uint4* srch = (const uint4*)(g_qh + (size_t)(b * NL + l0 + row) * CKD + h * DK);
        const int sw = (row >> 1) & 3;
        ((uint4*)qs_h)[row * 4 + (cp ^ sw)]       = srch[cp];
        ((uint4*)qs_h)[row * 4 + ((cp + 1) ^ sw)] = srch[cp + 1];
    }

    const __half* kg = g_kh + (size_t)(b * NH + h) * HWN * DK;
    const __half* vg = g_vh + ((size_t)b * CKD + h * DV) * HWN;
    const uint4* kg4 = (const uint4*)kg;
    const uint4* vg4 = (const uint4*)vg;

    const int krow = t >> 2, kck = t & 3;
    const int vrow = t >> 3, vck = t & 7;
    const uint32_t kd = (uint32_t)(krow * 4 + (kck ^ ((krow >> 1) & 3))) * 16;
    const uint32_t vd = (uint32_t)(vrow * 8 + (vck ^ (vrow & 7))) * 16;
    uint32_t kbB[3], vbB[3];
    #pragma unroll
    for (int p = 0; p < 3; p++) {
        kbB[p] = smem_u32(kb[p]);
        vbB[p] = smem_u32(vb[p]);
    }

    #pragma unroll
    for (int p = 0; p < 2; p++) {
        cpa16(kbB[p] + kd, kg4 + (p * 64 + krow) * 4 + kck);
        cpa16(vbB[p] + vd, vg4 + (size_t)vrow * (HWN / 8) + p * 8 + vck);
        CP_COMMIT();
    }
    __syncthreads();                     // qs_h visible

    uint32_t Ah[2][4];
    {
        const int row = (w << 4) + (lane & 7) + ((lane >> 3) & 1) * 8;
        const int kc  = lane >> 4;
        const int sw  = (row >> 1) & 3;
        #pragma unroll
        for (int s = 0; s < 2; s++) {
            const uint32_t off = (row * 4 + (((s << 1) + kc) ^ sw)) * 16;
            ldsm4(Ah[s], smem_u32(qs_h) + off);
        }
    }

    float O[4][4] = {};
    float ps0 = 0.f, ps1 = 0.f;
    int stage = 0;

    for (int c = 0; c < 64; c++) {
        if (c == 63) { CP_WAIT0(); } else { CP_WAIT1(); }
        __syncthreads();
        if (c < 62) {
            const int nx = (stage + 2 >= 3) ? stage - 1 : stage + 2;
            cpa16(kbB[nx] + kd, kg4 + ((c + 2) * 64 + krow) * 4 + kck);
            cpa16(vbB[nx] + vd, vg4 + (size_t)vrow * (HWN / 8) + (c + 2) * 8 + vck);
            CP_COMMIT();
        }
        const uint32_t ksb = kbB[stage], vsb = vbB[stage];

        float S[8][4];
        #pragma unroll
        for (int j = 0; j < 8; j++) { S[j][0]=0.f; S[j][1]=0.f; S[j][2]=0.f; S[j][3]=0.f; }
        #pragma unroll
        for (int j = 0; j < 8; j++) {
            const int row = (j << 3) + (lane & 7);
            uint32_t bk_[4];
            ldsm4(bk_, ksb + (row * 4 + ((lane >> 3) ^ ((row >> 1) & 3))) * 16);
            mma16816(S[j], Ah[0], bk_[0], bk_[1]);
            mma16816(S[j], Ah[1], bk_[2], bk_[3]);
        }

        uint32_t Ph[4][4];
        #pragma unroll
        for (int j = 0; j < 8; j++) {
            float p0 = ex2(S[j][0]), p1 = ex2(S[j][1]);
            float p2 = ex2(S[j][2]), p3 = ex2(S[j][3]);
            ps0 += p0 + p1;
            ps1 += p2 + p3;
            Ph[j >> 1][(j & 1) * 2 + 0] = h2pack(p0, p1);
            Ph[j >> 1][(j & 1) * 2 + 1] = h2pack(p2, p3);
        }

        #pragma unroll
        for (int j = 0; j < 4; j++) {
            #pragma unroll
            for (int s2 = 0; s2 < 2; s2++) {
                const int row = (j << 3) + (lane & 7);
                uint32_t bv_[4];
                ldsm4(bv_, vsb + (row * 8 + (((s2 << 2) + (lane >> 3)) ^ (row & 7))) * 16);
                mma16816(O[j], Ph[2 * s2],     bv_[0], bv_[1]);
                mma16816(O[j], Ph[2 * s2 + 1], bv_[2], bv_[3]);
            }
        }
        stage = (stage + 1 == 3) ? 0 : stage + 1;
    }

    ps0 += __shfl_xor_sync(0xffffffffu, ps0, 1);
    ps0 += __shfl_xor_sync(0xffffffffu, ps0, 2);
    ps1 += __shfl_xor_sync(0xffffffffu, ps1, 1);
    ps1 += __shfl_xor_sync(0xffffffffu, ps1, 2);
    const float inv0 = 1.0f / ps0, inv1 = 1.0f / ps1;

    const int r0 = l0 + (w << 4) + g;
    const size_t i0 = (size_t)(b * NL + r0) * CKD + h * DV + (l << 1);
    const size_t i1 = i0 + (size_t)8 * CKD;
    #pragma unroll
    for (int j = 0; j < 4; j++) {
        float a0 = O[j][0] * inv0, a1 = O[j][1] * inv0;
        float b0 = O[j][2] * inv1, b1 = O[j][3] * inv1;
        __half h0 = __float2half_rn(a0), h1 = __float2half_rn(a1);
        __half h2 = __float2half_rn(b0), h3 = __float2half_rn(b1);
        *(uint32_t*)&g_ath[i0 + (j << 3)] = h2pack(__half2float(h0), __half2float(h1));
        *(uint32_t*)&g_atl[i0 + (j << 3)] = h2pack(a0 - __half2float(h0), a1 - __half2float(h1));
        *(uint32_t*)&g_ath[i1 + (j << 3)] = h2pack(__half2float(h2), __half2float(h3));
        *(uint32_t*)&g_atl[i1 + (j << 3)] = h2pack(b0 - __half2float(h2), b1 - __half2float(h3));
    }
}

// ---------------------------------------------------------------------------
// InstanceNorm over Nl on g_y + transposed write out[b,l,o]
// ---------------------------------------------------------------------------
__global__ __launch_bounds__(256) void norm_t_kernel(float* __restrict__ out)
{
    __shared__ float tile[32][33];
    __shared__ float meanv[32], rstdv[32];
    const int b = blockIdx.y, o0 = blockIdx.x << 5;
    const int t = threadIdx.x, lane = t & 31, w = t >> 5;

    #pragma unroll
    for (int j = 0; j < 4; j++) {
        const int ol = (w << 2) + j;
        const float* yp = g_y + (size_t)(o0 + ol) * MTOT + b * NL;
        float s = 0.f, sq = 0.f;
        #pragma unroll
        for (int i = 0; i < 8; i++) {
            float4 v = *(const float4*)&yp[(i * 32 + lane) * 4];
            s  += v.x + v.y + v.z + v.w;
            sq += v.x*v.x + v.y*v.y + v.z*v.z + v.w*v.w;
        }
        #pragma unroll
        for (int off = 16; off; off >>= 1) {
            s  += __shfl_xor_sync(0xffffffffu, s,  off);
            sq += __shfl_xor_sync(0xffffffffu, sq, off);
        }
        if (lane == 0) {
            float mean = s * (1.f / NL);
            float var  = sq * (1.f / NL) - mean * mean;
            meanv[ol] = mean;
            rstdv[ol] = rsqrtf(var + EPSI);
        }
    }
    __syncthreads();
    const float mo = meanv[lane], ro = rstdv[lane];
    for (int l0 = 0; l0 < NL; l0 += 32) {
        __syncthreads();
        #pragma unroll
        for (int j = 0; j < 4; j++)
            tile[w + 8*j][lane] =
                g_y[(size_t)(o0 + w + 8*j) * MTOT + b * NL + l0 + lane];
        __syncthreads();
        #pragma unroll
        for (int j = 0; j < 4; j++)
            out[(size_t)(b * NL + l0 + w + 8*j) * CKD + o0 + lane] =
                (tile[lane][w + 8*j] - mo) * ro;
    }
}

// ---------------------------------------------------------------------------
extern "C" void kernel_launch(void* const* d_in, const int* in_sizes, int n_in,
                              void* d_out, int out_size)
{
    const float* l  = (const float*)d_in[0];
    const float* x  = (const float*)d_in[1];
    const float* Wq = (const float*)d_in[2];
    const float* bq = (const float*)d_in[3];
    const float* Wk = (const float*)d_in[4];
    const float* Wv = (const float*)d_in[6];
    const float* bv = (const float*)d_in[7];
    const float* Ww = (const float*)d_in[8];
    float* out = (float*)d_out;

    cudaFuncSetAttribute(gemm_q_hmma,
                         cudaFuncAttributeMaxDynamicSharedMemorySize, S1_SMEM);
    cudaFuncSetAttribute(gemm_kv_hmma,
                         cudaFuncAttributeMaxDynamicSharedMemorySize, S1_SMEM);
    cudaFuncSetAttribute(gemm_proj_hmma,
                         cudaFuncAttributeMaxDynamicSharedMemorySize, S2_SMEM);

    split_w_kernel    <<<512, 256>>>(Wk, Wv);
    split_wq_kernel   <<<CKD, 256>>>(Wq);
    split_ww_kernel   <<<CKD, 128>>>(Ww);
    split_xl_kernel   <<<XBLOCKS + LBLOCKS, 256>>>(x, l);
    gemm_q_hmma       <<<dim3(MTOT / 128, CKD / 64), 256, S1_SMEM>>>(bq);
    gemm_kv_hmma      <<<dim3(HWN / 128, 8, BATCH), 256, S1_SMEM>>>(bv);
    inorm_stats_kernel<<<BATCH * CKD, 256>>>();
    convert_k_kernel  <<<dim3(HWN / 128, NH, BATCH), 256>>>();
    attn_hmma_kernel  <<<dim3(NL / 128, NH, BATCH), 256>>>();
    gemm_proj_hmma    <<<dim3(MTOT / 128, CKD / 64), 256, S2_SMEM>>>();
    norm_t_kernel     <<<dim3(CKD / 32, BATCH), 256>>>(out);
}